// round 13
// baseline (speedup 1.0000x reference)
#include <cuda_runtime.h>
#include <cstdint>

#define HID 2048
#define SEQ 2048
#define BATCH 2
#define NH 32
#define NKV 8
#define HD 64
#define KVD 512
#define MROWS (BATCH*SEQ)

// Scratch (allocation-free: __device__ globals)
__device__ float g_Q[MROWS * HID];   // 32 MB
__device__ float g_K[MROWS * KVD];   //  8 MB
__device__ float g_V[MROWS * KVD];   //  8 MB
__device__ float g_C[MROWS * HID];   // 32 MB

__device__ __forceinline__ unsigned f2tf(float f) {
    unsigned u;
    asm("cvt.rna.tf32.f32 %0, %1;" : "=r"(u) : "f"(f));
    return u;
}

__device__ __forceinline__ uint32_t smem_u32(const void* p) {
    uint32_t a;
    asm("{ .reg .u64 t; cvta.to.shared.u64 t, %1; cvt.u32.u64 %0, t; }" : "=r"(a) : "l"(p));
    return a;
}

#define CP_ASYNC16(dst, src) \
    asm volatile("cp.async.cg.shared.global [%0], [%1], 16;" :: "r"(dst), "l"(src))
#define CP_COMMIT() asm volatile("cp.async.commit_group;" ::: "memory")
#define CP_WAIT0()  asm volatile("cp.async.wait_group 0;"  ::: "memory")

__device__ __forceinline__ void mma8(float* d, const unsigned* a, unsigned b0, unsigned b1) {
    asm volatile(
        "mma.sync.aligned.m16n8k8.row.col.f32.tf32.tf32.f32 "
        "{%0,%1,%2,%3}, {%4,%5,%6,%7}, {%8,%9}, {%0,%1,%2,%3};"
        : "+f"(d[0]), "+f"(d[1]), "+f"(d[2]), "+f"(d[3])
        : "r"(a[0]), "r"(a[1]), "r"(a[2]), "r"(a[3]), "r"(b0), "r"(b1));
}

// ============================================================================
// GEMM: Y[M][N-slice] = X[M][K] @ W[N][K]^T + bias.
// CTA tile 128x128, K tile 32, 8 warps = 4(m) x 2(n), warp tile 32x64
// (mt=2, nt=8, acc=64 regs). Double-buffered cp.async; raw fp32 in smem,
// cvt.rna.tf32 at fragment load (same RNA math as before).
// __launch_bounds__(256, 2): 2 CTAs/SM -> 16 warps/SM, barriers/epilogue of
// one CTA overlap the mma stream of the other.
// ============================================================================
#define GEMM_BUF (256 * 36)                 // floats per buffer (X:128 + W:128, stride 36)
#define GEMM_SMEM (2 * GEMM_BUF * 4)        // 73728 B -> 2 CTAs/SM

__device__ __forceinline__
void gemm_copy_async(float* Xb, float* Wb, const float* __restrict__ Xg,
                     const float* __restrict__ Wg, int K, int ko, int tid)
{
    const int lr = tid >> 3;           // 0..31
    const int lc = (tid & 7) << 2;     // 0,4,...,28
    #pragma unroll
    for (int i = 0; i < 4; i++) {
        int row = lr + i * 32;
        CP_ASYNC16(smem_u32(&Xb[row * 36 + lc]), &Xg[(size_t)row * K + ko + lc]);
    }
    #pragma unroll
    for (int i = 0; i < 4; i++) {
        int row = lr + i * 32;
        CP_ASYNC16(smem_u32(&Wb[row * 36 + lc]), &Wg[(size_t)row * K + ko + lc]);
    }
}

__device__ __forceinline__
void gemm_body(const float* __restrict__ X, const float* __restrict__ W,
               const float* __restrict__ bias, float* __restrict__ Y,
               int N, int K, int mBase, int nBase, float* sm)
{
    const int tid  = threadIdx.x;
    const int w    = tid >> 5;
    const int lane = tid & 31;
    const int gp   = lane >> 2;
    const int tq   = lane & 3;
    const int wm   = w & 3;        // 0..3  (32-row slabs)
    const int wn   = w >> 2;       // 0..1  (64-col slabs)

    const float* Xg = X + (size_t)mBase * K;
    const float* Wg = W + (size_t)nBase * K;

    float acc[2][8][4];
    #pragma unroll
    for (int i = 0; i < 2; i++)
        #pragma unroll
        for (int j = 0; j < 8; j++)
            #pragma unroll
            for (int t = 0; t < 4; t++) acc[i][j][t] = 0.f;

    const int NT = K / 32;

    // prologue: tile 0 -> buf 0
    gemm_copy_async(sm, sm + 128 * 36, Xg, Wg, K, 0, tid);
    CP_COMMIT(); CP_WAIT0();
    __syncthreads();

    for (int t = 0; t < NT; t++) {
        float* Xb = sm + (t & 1) * GEMM_BUF;
        float* Wb = Xb + 128 * 36;
        if (t + 1 < NT) {
            float* Xn = sm + ((t + 1) & 1) * GEMM_BUF;
            gemm_copy_async(Xn, Xn + 128 * 36, Xg, Wg, K, (t + 1) * 32, tid);
            CP_COMMIT();
        }

        #pragma unroll
        for (int kk = 0; kk < 4; kk++) {
            const int kb = kk * 8;
            unsigned a[2][4];
            #pragma unroll
            for (int mt = 0; mt < 2; mt++) {
                int r = wm * 32 + mt * 16 + gp;
                a[mt][0] = f2tf(Xb[r * 36 + kb + tq]);
                a[mt][1] = f2tf(Xb[(r + 8) * 36 + kb + tq]);
                a[mt][2] = f2tf(Xb[r * 36 + kb + tq + 4]);
                a[mt][3] = f2tf(Xb[(r + 8) * 36 + kb + tq + 4]);
            }
            unsigned bb[8][2];
            #pragma unroll
            for (int nt = 0; nt < 8; nt++) {
                int r = wn * 64 + nt * 8 + gp;
                bb[nt][0] = f2tf(Wb[r * 36 + kb + tq]);
                bb[nt][1] = f2tf(Wb[r * 36 + kb + tq + 4]);
            }
            #pragma unroll
            for (int mt = 0; mt < 2; mt++)
                #pragma unroll
                for (int nt = 0; nt < 8; nt++)
                    mma8(acc[mt][nt], a[mt], bb[nt][0], bb[nt][1]);
        }

        if (t + 1 < NT) CP_WAIT0();
        __syncthreads();
    }

    #pragma unroll
    for (int mt = 0; mt < 2; mt++) {
        int row = mBase + wm * 32 + mt * 16 + gp;
        #pragma unroll
        for (int nt = 0; nt < 8; nt++) {
            int col = nBase + wn * 64 + nt * 8 + tq * 2;
            float b0 = bias[col], b1 = bias[col + 1];
            *(float2*)&Y[(size_t)row * N + col] =
                make_float2(acc[mt][nt][0] + b0, acc[mt][nt][1] + b1);
            *(float2*)&Y[(size_t)(row + 8) * N + col] =
                make_float2(acc[mt][nt][2] + b0, acc[mt][nt][3] + b1);
        }
    }
}

__global__ __launch_bounds__(256, 2)
void gemm_v2(const float* __restrict__ X, const float* __restrict__ W,
             const float* __restrict__ bias, float* __restrict__ Y,
             int N, int K)
{
    extern __shared__ float fsm[];
    gemm_body(X, W, bias, Y, N, K, blockIdx.y * 128, blockIdx.x * 128, fsm);
}

// K and V projections fused into one launch (grid.x = 8: 0-3 -> K, 4-7 -> V)
__global__ __launch_bounds__(256, 2)
void gemm_kv(const float* __restrict__ X,
             const float* __restrict__ Wk, const float* __restrict__ bk, float* __restrict__ Yk,
             const float* __restrict__ Wv, const float* __restrict__ bv, float* __restrict__ Yv,
             int N, int K)
{
    extern __shared__ float fsm[];
    if (blockIdx.x < 4)
        gemm_body(X, Wk, bk, Yk, N, K, blockIdx.y * 128, blockIdx.x * 128, fsm);
    else
        gemm_body(X, Wv, bv, Yv, N, K, blockIdx.y * 128, (blockIdx.x - 4) * 128, fsm);
}

// ============================================================================
// Flash attention, TF32 mma (unchanged from R11-passing version).
// One CTA = one (batch, head, 256-row Q tile). 8 warps x 32 Q rows (mt=2).
// Double-buffered cp.async K/V pipeline; Ks stride 68, Vs stride 72,
// Ps stride 68 — all conflict-free. grid = 512.
// ============================================================================
#define KBUF (64 * 68)
#define VBUF (64 * 72)
#define ATTN_SMEM ((2*KBUF + 2*VBUF + 256*68) * 4)   // 141312 B

__device__ __forceinline__
void attn_copy_async(float* Kb, float* Vb, const float* __restrict__ Kh,
                     const float* __restrict__ Vh, int kt, int tid)
{
    #pragma unroll
    for (int i = 0; i < 4; i++) {
        int idx = tid + i * 256;
        int r = idx >> 4;
        int c = (idx & 15) << 2;
        size_t g = (size_t)(kt * 64 + r) * KVD + c;
        CP_ASYNC16(smem_u32(&Kb[r * 68 + c]), &Kh[g]);
        CP_ASYNC16(smem_u32(&Vb[r * 72 + c]), &Vh[g]);
    }
}

__global__ __launch_bounds__(256, 1)
void attn_tf32(const float* __restrict__ Q, const float* __restrict__ Kg,
               const float* __restrict__ Vg, float* __restrict__ C)
{
    extern __shared__ float fsm[];
    float* K0 = fsm;
    float* K1 = K0 + KBUF;
    float* V0 = K1 + KBUF;
    float* V1 = V0 + VBUF;
    unsigned* PsP = (unsigned*)(V1 + VBUF);   // [256][68] tf32

    const int tid  = threadIdx.x;
    const int w    = tid >> 5;
    const int lane = tid & 31;
    const int gp   = lane >> 2;
    const int tq   = lane & 3;

    const int bid = blockIdx.x;
    const int qt  = bid & 7;
    const int h   = (bid >> 3) & 31;
    const int b   = bid >> 8;
    const int hk  = h >> 2;               // repeat_interleave: kv head = h/4
    const int qbase = qt * 256 + w * 32;

    const float* Kh = Kg + (size_t)b * SEQ * KVD + hk * HD;
    const float* Vh = Vg + (size_t)b * SEQ * KVD + hk * HD;

    // prologue: KV tile 0 -> buf 0
    attn_copy_async(K0, V0, Kh, Vh, 0, tid);
    CP_COMMIT();

    // Q fragments: 2 m-tiles x 8 k-steps, loaded once (overlaps prologue copy)
    unsigned qa[2][8][4];
    #pragma unroll
    for (int mt = 0; mt < 2; mt++) {
        const float* qp0 = Q + (size_t)(b * SEQ + qbase + mt * 16 + gp) * HID + h * HD;
        const float* qp1 = qp0 + (size_t)8 * HID;
        #pragma unroll
        for (int ks = 0; ks < 8; ks++) {
            int d = ks * 8 + tq;
            qa[mt][ks][0] = f2tf(qp0[d]);
            qa[mt][ks][1] = f2tf(qp1[d]);
            qa[mt][ks][2] = f2tf(qp0[d + 4]);
            qa[mt][ks][3] = f2tf(qp1[d + 4]);
        }
    }

    float o[2][8][4];
    #pragma unroll
    for (int mt = 0; mt < 2; mt++)
        #pragma unroll
        for (int i = 0; i < 8; i++)
            #pragma unroll
            for (int j = 0; j < 4; j++) o[mt][i][j] = 0.f;
    float mrow[2][2] = {{-1e30f, -1e30f}, {-1e30f, -1e30f}};
    float lrow[2][2] = {{0.f, 0.f}, {0.f, 0.f}};

    CP_WAIT0();
    __syncthreads();

    for (int kt = 0; kt < 32; kt++) {
        float* Kb = (kt & 1) ? K1 : K0;
        float* Vb = (kt & 1) ? V1 : V0;
        if (kt + 1 < 32) {
            attn_copy_async((kt & 1) ? K0 : K1, (kt & 1) ? V0 : V1, Kh, Vh, kt + 1, tid);
            CP_COMMIT();
        }

        // S = Q K^T  (32 q-rows x 64 kv per warp; B frags shared across mt)
        float s[2][8][4];
        #pragma unroll
        for (int mt = 0; mt < 2; mt++)
            #pragma unroll
            for (int i = 0; i < 8; i++)
                #pragma unroll
                for (int j = 0; j < 4; j++) s[mt][i][j] = 0.f;
        #pragma unroll
        for (int ks = 0; ks < 8; ks++) {
            unsigned bb[8][2];
            #pragma unroll
            for (int nt = 0; nt < 8; nt++) {
                bb[nt][0] = f2tf(Kb[(nt * 8 + gp) * 68 + ks * 8 + tq]);
                bb[nt][1] = f2tf(Kb[(nt * 8 + gp) * 68 + ks * 8 + tq + 4]);
            }
            #pragma unroll
            for (int mt = 0; mt < 2; mt++)
                #pragma unroll
                for (int nt = 0; nt < 8; nt++)
                    mma8(s[mt][nt], qa[mt][ks], bb[nt][0], bb[nt][1]);
        }

        // online softmax per m-tile (scale = 1/sqrt(64) = 0.125 exactly)
        #pragma unroll
        for (int mt = 0; mt < 2; mt++) {
            float mx0 = -1e30f, mx1 = -1e30f;
            #pragma unroll
            for (int nt = 0; nt < 8; nt++) {
                s[mt][nt][0] *= 0.125f; s[mt][nt][1] *= 0.125f;
                s[mt][nt][2] *= 0.125f; s[mt][nt][3] *= 0.125f;
                mx0 = fmaxf(mx0, fmaxf(s[mt][nt][0], s[mt][nt][1]));
                mx1 = fmaxf(mx1, fmaxf(s[mt][nt][2], s[mt][nt][3]));
            }
            mx0 = fmaxf(mx0, __shfl_xor_sync(0xffffffffu, mx0, 1));
            mx0 = fmaxf(mx0, __shfl_xor_sync(0xffffffffu, mx0, 2));
            mx1 = fmaxf(mx1, __shfl_xor_sync(0xffffffffu, mx1, 1));
            mx1 = fmaxf(mx1, __shfl_xor_sync(0xffffffffu, mx1, 2));
            float mn0 = fmaxf(mrow[mt][0], mx0), mn1 = fmaxf(mrow[mt][1], mx1);
            float al0 = __expf(mrow[mt][0] - mn0), al1 = __expf(mrow[mt][1] - mn1);
            mrow[mt][0] = mn0; mrow[mt][1] = mn1;

            const int pr = w * 32 + mt * 16 + gp;
            float rs0 = 0.f, rs1 = 0.f;
            #pragma unroll
            for (int nt = 0; nt < 8; nt++) {
                float p0 = __expf(s[mt][nt][0] - mn0), p1 = __expf(s[mt][nt][1] - mn0);
                float p2 = __expf(s[mt][nt][2] - mn1), p3 = __expf(s[mt][nt][3] - mn1);
                rs0 += p0 + p1; rs1 += p2 + p3;
                int pc = nt * 8 + tq * 2;
                PsP[pr * 68 + pc]           = f2tf(p0);
                PsP[pr * 68 + pc + 1]       = f2tf(p1);
                PsP[(pr + 8) * 68 + pc]     = f2tf(p2);
                PsP[(pr + 8) * 68 + pc + 1] = f2tf(p3);
            }
            rs0 += __shfl_xor_sync(0xffffffffu, rs0, 1);
            rs0 += __shfl_xor_sync(0xffffffffu, rs0, 2);
            rs1 += __shfl_xor_sync(0xffffffffu, rs1, 1);
            rs1 += __shfl_xor_sync(0xffffffffu, rs1, 2);
            lrow[mt][0] = lrow[mt][0] * al0 + rs0;
            lrow[mt][1] = lrow[mt][1] * al1 + rs1;
            #pragma unroll
            for (int nt = 0; nt < 8; nt++) {
                o[mt][nt][0] *= al0; o[mt][nt][1] *= al0;
                o[mt][nt][2] *= al1; o[mt][nt][3] *= al1;
            }
        }
        __syncwarp();   // Ps rows are warp-private

        // O += P V   (V frags shared across mt)
        #pragma unroll
        for (int ks = 0; ks < 8; ks++) {
            unsigned a[2][4];
            #pragma unroll
            for (int mt = 0; mt < 2; mt++) {
                const int pr = w * 32 + mt * 16 + gp;
                a[mt][0] = PsP[pr * 68 + ks * 8 + tq];
                a[mt][1] = PsP[(pr + 8) * 68 + ks * 8 + tq];
                a[mt][2] = PsP[pr * 68 + ks * 8 + tq + 4];
                a[mt][3] = PsP[(pr + 8) * 68 + ks * 8 + tq + 4];
            }
            #pragma unroll
            for (int nt = 0; nt < 8; nt++) {
                unsigned b0 = f2tf(Vb[(ks * 8 + tq) * 72 + nt * 8 + gp]);
                unsigned b1 = f2tf(Vb[(ks * 8 + tq + 4) * 72 + nt * 8 + gp]);
                #pragma unroll
                for (int mt = 0; mt < 2; mt++)
                    mma8(o[mt][nt], a[mt], b0, b1);
            }
        }

        if (kt + 1 < 32) CP_WAIT0();
        __syncthreads();
    }

    // epilogue: normalize and scatter to context layout [b, s, h*d]
    #pragma unroll
    for (int mt = 0; mt < 2; mt++) {
        float inv0 = 1.f / lrow[mt][0], inv1 = 1.f / lrow[mt][1];
        float* cp0 = C + (size_t)(b * SEQ + qbase + mt * 16 + gp) * HID + h * HD;
        float* cp1 = cp0 + (size_t)8 * HID;
        #pragma unroll
        for (int nt = 0; nt < 8; nt++) {
            int d = nt * 8 + tq * 2;
            *(float2*)&cp0[d] = make_float2(o[mt][nt][0] * inv0, o[mt][nt][1] * inv0);
            *(float2*)&cp1[d] = make_float2(o[mt][nt][2] * inv1, o[mt][nt][3] * inv1);
        }
    }
}

// ============================================================================
// Launch
// ============================================================================
extern "C" void kernel_launch(void* const* d_in, const int* in_sizes, int n_in,
                              void* d_out, int out_size)
{
    const float* x  = (const float*)d_in[0];
    const float* wq = (const float*)d_in[1];
    const float* bq = (const float*)d_in[2];
    const float* wk = (const float*)d_in[3];
    const float* bk = (const float*)d_in[4];
    const float* wv = (const float*)d_in[5];
    const float* bv = (const float*)d_in[6];
    const float* wo = (const float*)d_in[7];
    const float* bo = (const float*)d_in[8];
    float* out = (float*)d_out;

    float *Qp, *Kp, *Vp, *Cp;
    cudaGetSymbolAddress((void**)&Qp, g_Q);
    cudaGetSymbolAddress((void**)&Kp, g_K);
    cudaGetSymbolAddress((void**)&Vp, g_V);
    cudaGetSymbolAddress((void**)&Cp, g_C);

    cudaFuncSetAttribute(gemm_v2,  cudaFuncAttributeMaxDynamicSharedMemorySize, GEMM_SMEM);
    cudaFuncSetAttribute(gemm_kv,  cudaFuncAttributeMaxDynamicSharedMemorySize, GEMM_SMEM);
    cudaFuncSetAttribute(attn_tf32, cudaFuncAttributeMaxDynamicSharedMemorySize, ATTN_SMEM);

    dim3 thr(256);
    // Q projection: grid (16, 32) = 512 CTAs, 2/SM
    gemm_v2<<<dim3(HID / 128, MROWS / 128), thr, GEMM_SMEM>>>(x, wq, bq, Qp, HID, HID);
    // K + V projections fused: grid (8, 32) = 256 CTAs
    gemm_kv<<<dim3(2 * KVD / 128, MROWS / 128), thr, GEMM_SMEM>>>(
        x, wk, bk, Kp, wv, bv, Vp, KVD, HID);
    // attention: 512 CTAs
    attn_tf32<<<BATCH * NH * (SEQ / 256), thr, ATTN_SMEM>>>(Qp, Kp, Vp, Cp);
    // output projection
    gemm_v2<<<dim3(HID / 128, MROWS / 128), thr, GEMM_SMEM>>>(Cp, wo, bo, out, HID, HID);
}

// round 15
// speedup vs baseline: 1.1212x; 1.1212x over previous
#include <cuda_runtime.h>
#include <cstdint>

#define HID 2048
#define SEQ 2048
#define BATCH 2
#define NH 32
#define NKV 8
#define HD 64
#define KVD 512
#define MROWS (BATCH*SEQ)

// Scratch (allocation-free: __device__ globals)
__device__ float g_Q[MROWS * HID];    // 32 MB  (tf32 bits)
__device__ float g_K[MROWS * KVD];    //  8 MB  (tf32 bits)
__device__ float g_V[MROWS * KVD];    //  8 MB  (tf32 bits)
__device__ float g_C[MROWS * HID];    // 32 MB  (tf32 bits)
__device__ float g_xt[MROWS * HID];   // 16 MB  x  -> tf32 bits
__device__ float g_wqt[HID * HID];    // 16 MB  wq -> tf32 bits
__device__ float g_wkt[KVD * HID];    //  4 MB
__device__ float g_wvt[KVD * HID];    //  4 MB
__device__ float g_wot[HID * HID];    // 16 MB

__device__ __forceinline__ unsigned f2tf(float f) {
    unsigned u;
    asm("cvt.rna.tf32.f32 %0, %1;" : "=r"(u) : "f"(f));
    return u;
}

__device__ __forceinline__ uint32_t smem_u32(const void* p) {
    uint32_t a;
    asm("{ .reg .u64 t; cvta.to.shared.u64 t, %1; cvt.u32.u64 %0, t; }" : "=r"(a) : "l"(p));
    return a;
}

#define CP_ASYNC16(dst, src) \
    asm volatile("cp.async.cg.shared.global [%0], [%1], 16;" :: "r"(dst), "l"(src))
#define CP_COMMIT() asm volatile("cp.async.commit_group;" ::: "memory")
#define CP_WAIT0()  asm volatile("cp.async.wait_group 0;"  ::: "memory")

__device__ __forceinline__ void mma8(float* d, const unsigned* a, unsigned b0, unsigned b1) {
    asm volatile(
        "mma.sync.aligned.m16n8k8.row.col.f32.tf32.tf32.f32 "
        "{%0,%1,%2,%3}, {%4,%5,%6,%7}, {%8,%9}, {%0,%1,%2,%3};"
        : "+f"(d[0]), "+f"(d[1]), "+f"(d[2]), "+f"(d[3])
        : "r"(a[0]), "r"(a[1]), "r"(a[2]), "r"(a[3]), "r"(b0), "r"(b1));
}

// ============================================================================
// Pre-pass: elementwise cvt.rna.tf32 of a fp32 tensor (bits stored as fp32).
// ============================================================================
__global__ __launch_bounds__(256)
void cvt_tf32(const float4* __restrict__ in, float4* __restrict__ out, int n4)
{
    int i = blockIdx.x * 256 + threadIdx.x;
    if (i < n4) {
        float4 v = in[i];
        float4 o;
        o.x = __uint_as_float(f2tf(v.x));
        o.y = __uint_as_float(f2tf(v.y));
        o.z = __uint_as_float(f2tf(v.z));
        o.w = __uint_as_float(f2tf(v.w));
        out[i] = o;
    }
}

// ============================================================================
// GEMM: Y[M][N-slice] = X[M][K] @ W[N][K]^T + bias.
// X and W hold tf32 bit patterns (pre-converted) -> NO cvt in the mainloop.
// CTA tile 128x256, K tile 32, warp tile 64x64 (mt=4, nt=8).
// Double-buffered cp.async. CVT_OUT: epilogue writes tf32-converted values
// (exactly what the consumer's fragment load used to compute).
// ============================================================================
#define GEMM_BUF (384 * 36)                 // floats per buffer (X:128 + W:256, stride 36)
#define GEMM_SMEM (2 * GEMM_BUF * 4)        // 110592 B

__device__ __forceinline__
void gemm_copy_async(float* Xb, float* Wb, const float* __restrict__ Xg,
                     const float* __restrict__ Wg, int K, int ko, int tid)
{
    const int lr = tid >> 3;           // 0..31
    const int lc = (tid & 7) << 2;     // 0,4,...,28
    #pragma unroll
    for (int i = 0; i < 4; i++) {
        int row = lr + i * 32;
        CP_ASYNC16(smem_u32(&Xb[row * 36 + lc]), &Xg[(size_t)row * K + ko + lc]);
    }
    #pragma unroll
    for (int i = 0; i < 8; i++) {
        int row = lr + i * 32;
        CP_ASYNC16(smem_u32(&Wb[row * 36 + lc]), &Wg[(size_t)row * K + ko + lc]);
    }
}

template<int CVT_OUT>
__device__ __forceinline__
void gemm_body(const float* __restrict__ X, const float* __restrict__ W,
               const float* __restrict__ bias, float* __restrict__ Y,
               int N, int K, int mBase, int nBase, float* sm)
{
    const int tid  = threadIdx.x;
    const int w    = tid >> 5;
    const int lane = tid & 31;
    const int gp   = lane >> 2;
    const int tq   = lane & 3;
    const int wm   = w & 1;        // 0..1  (64-row slabs)
    const int wn   = w >> 1;       // 0..3  (64-col slabs)

    const float* Xg = X + (size_t)mBase * K;
    const float* Wg = W + (size_t)nBase * K;

    float acc[4][8][4];
    #pragma unroll
    for (int i = 0; i < 4; i++)
        #pragma unroll
        for (int j = 0; j < 8; j++)
            #pragma unroll
            for (int t = 0; t < 4; t++) acc[i][j][t] = 0.f;

    const int NT = K / 32;

    // prologue: tile 0 -> buf 0
    gemm_copy_async(sm, sm + 128 * 36, Xg, Wg, K, 0, tid);
    CP_COMMIT(); CP_WAIT0();
    __syncthreads();

    for (int t = 0; t < NT; t++) {
        const unsigned* Xb = (const unsigned*)(sm + (t & 1) * GEMM_BUF);
        const unsigned* Wb = Xb + 128 * 36;
        if (t + 1 < NT) {
            float* Xn = sm + ((t + 1) & 1) * GEMM_BUF;
            gemm_copy_async(Xn, Xn + 128 * 36, Xg, Wg, K, (t + 1) * 32, tid);
            CP_COMMIT();
        }

        #pragma unroll
        for (int kk = 0; kk < 4; kk++) {
            const int kb = kk * 8;
            unsigned a[4][4];
            #pragma unroll
            for (int mt = 0; mt < 4; mt++) {
                int r = wm * 64 + mt * 16 + gp;
                a[mt][0] = Xb[r * 36 + kb + tq];
                a[mt][1] = Xb[(r + 8) * 36 + kb + tq];
                a[mt][2] = Xb[r * 36 + kb + tq + 4];
                a[mt][3] = Xb[(r + 8) * 36 + kb + tq + 4];
            }
            unsigned bb[8][2];
            #pragma unroll
            for (int nt = 0; nt < 8; nt++) {
                int r = wn * 64 + nt * 8 + gp;
                bb[nt][0] = Wb[r * 36 + kb + tq];
                bb[nt][1] = Wb[r * 36 + kb + tq + 4];
            }
            #pragma unroll
            for (int mt = 0; mt < 4; mt++)
                #pragma unroll
                for (int nt = 0; nt < 8; nt++)
                    mma8(acc[mt][nt], a[mt], bb[nt][0], bb[nt][1]);
        }

        if (t + 1 < NT) CP_WAIT0();
        __syncthreads();
    }

    #pragma unroll
    for (int mt = 0; mt < 4; mt++) {
        int row = mBase + wm * 64 + mt * 16 + gp;
        #pragma unroll
        for (int nt = 0; nt < 8; nt++) {
            int col = nBase + wn * 64 + nt * 8 + tq * 2;
            float b0 = bias[col], b1 = bias[col + 1];
            float y00 = acc[mt][nt][0] + b0, y01 = acc[mt][nt][1] + b1;
            float y10 = acc[mt][nt][2] + b0, y11 = acc[mt][nt][3] + b1;
            if (CVT_OUT) {
                y00 = __uint_as_float(f2tf(y00)); y01 = __uint_as_float(f2tf(y01));
                y10 = __uint_as_float(f2tf(y10)); y11 = __uint_as_float(f2tf(y11));
            }
            *(float2*)&Y[(size_t)row * N + col]       = make_float2(y00, y01);
            *(float2*)&Y[(size_t)(row + 8) * N + col] = make_float2(y10, y11);
        }
    }
}

__global__ __launch_bounds__(256, 1)
void gemm_q(const float* __restrict__ X, const float* __restrict__ W,
            const float* __restrict__ bias, float* __restrict__ Y,
            int N, int K)
{
    extern __shared__ float fsm[];
    gemm_body<1>(X, W, bias, Y, N, K, blockIdx.y * 128, blockIdx.x * 256, fsm);
}

__global__ __launch_bounds__(256, 1)
void gemm_o(const float* __restrict__ X, const float* __restrict__ W,
            const float* __restrict__ bias, float* __restrict__ Y,
            int N, int K)
{
    extern __shared__ float fsm[];
    gemm_body<0>(X, W, bias, Y, N, K, blockIdx.y * 128, blockIdx.x * 256, fsm);
}

// K and V projections fused into one launch (grid.x = 4: 0-1 -> K, 2-3 -> V)
__global__ __launch_bounds__(256, 1)
void gemm_kv(const float* __restrict__ X,
             const float* __restrict__ Wk, const float* __restrict__ bk, float* __restrict__ Yk,
             const float* __restrict__ Wv, const float* __restrict__ bv, float* __restrict__ Yv,
             int N, int K)
{
    extern __shared__ float fsm[];
    if (blockIdx.x < 2)
        gemm_body<1>(X, Wk, bk, Yk, N, K, blockIdx.y * 128, blockIdx.x * 256, fsm);
    else
        gemm_body<1>(X, Wv, bv, Yv, N, K, blockIdx.y * 128, (blockIdx.x - 2) * 256, fsm);
}

// ============================================================================
// Flash attention. Q/K/V hold tf32 bit patterns -> fragment loads need NO cvt
// (only P, produced in-kernel, is cvt'd before the PV mma). Epilogue writes
// C as tf32 bits for the O-projection. Math identical to previous rounds.
// One CTA = one (batch, head, 256-row Q tile). 8 warps x 32 Q rows (mt=2).
// Ks stride 68, Vs stride 72, Ps stride 68 — all conflict-free. grid = 512.
// ============================================================================
#define KBUF (64 * 68)
#define VBUF (64 * 72)
#define ATTN_SMEM ((2*KBUF + 2*VBUF + 256*68) * 4)   // 141312 B

__device__ __forceinline__
void attn_copy_async(float* Kb, float* Vb, const float* __restrict__ Kh,
                     const float* __restrict__ Vh, int kt, int tid)
{
    #pragma unroll
    for (int i = 0; i < 4; i++) {
        int idx = tid + i * 256;
        int r = idx >> 4;
        int c = (idx & 15) << 2;
        size_t g = (size_t)(kt * 64 + r) * KVD + c;
        CP_ASYNC16(smem_u32(&Kb[r * 68 + c]), &Kh[g]);
        CP_ASYNC16(smem_u32(&Vb[r * 72 + c]), &Vh[g]);
    }
}

__global__ __launch_bounds__(256, 1)
void attn_tf32(const float* __restrict__ Q, const float* __restrict__ Kg,
               const float* __restrict__ Vg, float* __restrict__ C)
{
    extern __shared__ float fsm[];
    float* K0 = fsm;
    float* K1 = K0 + KBUF;
    float* V0 = K1 + KBUF;
    float* V1 = V0 + VBUF;
    unsigned* PsP = (unsigned*)(V1 + VBUF);   // [256][68] tf32

    const int tid  = threadIdx.x;
    const int w    = tid >> 5;
    const int lane = tid & 31;
    const int gp   = lane >> 2;
    const int tq   = lane & 3;

    const int bid = blockIdx.x;
    const int qt  = bid & 7;
    const int h   = (bid >> 3) & 31;
    const int b   = bid >> 8;
    const int hk  = h >> 2;               // repeat_interleave: kv head = h/4
    const int qbase = qt * 256 + w * 32;

    const float* Kh = Kg + (size_t)b * SEQ * KVD + hk * HD;
    const float* Vh = Vg + (size_t)b * SEQ * KVD + hk * HD;

    // prologue: KV tile 0 -> buf 0
    attn_copy_async(K0, V0, Kh, Vh, 0, tid);
    CP_COMMIT();

    // Q fragments (already tf32 bits): 2 m-tiles x 8 k-steps, loaded once
    unsigned qa[2][8][4];
    #pragma unroll
    for (int mt = 0; mt < 2; mt++) {
        const unsigned* qp0 = (const unsigned*)(Q + (size_t)(b * SEQ + qbase + mt * 16 + gp) * HID + h * HD);
        const unsigned* qp1 = qp0 + (size_t)8 * HID;
        #pragma unroll
        for (int ks = 0; ks < 8; ks++) {
            int d = ks * 8 + tq;
            qa[mt][ks][0] = qp0[d];
            qa[mt][ks][1] = qp1[d];
            qa[mt][ks][2] = qp0[d + 4];
            qa[mt][ks][3] = qp1[d + 4];
        }
    }

    float o[2][8][4];
    #pragma unroll
    for (int mt = 0; mt < 2; mt++)
        #pragma unroll
        for (int i = 0; i < 8; i++)
            #pragma unroll
            for (int j = 0; j < 4; j++) o[mt][i][j] = 0.f;
    float mrow[2][2] = {{-1e30f, -1e30f}, {-1e30f, -1e30f}};
    float lrow[2][2] = {{0.f, 0.f}, {0.f, 0.f}};

    CP_WAIT0();
    __syncthreads();

    for (int kt = 0; kt < 32; kt++) {
        const unsigned* Kb = (const unsigned*)((kt & 1) ? K1 : K0);
        const unsigned* Vb = (const unsigned*)((kt & 1) ? V1 : V0);
        if (kt + 1 < 32) {
            attn_copy_async((kt & 1) ? K0 : K1, (kt & 1) ? V0 : V1, Kh, Vh, kt + 1, tid);
            CP_COMMIT();
        }

        // S = Q K^T  (32 q-rows x 64 kv per warp; B frags shared across mt)
        float s[2][8][4];
        #pragma unroll
        for (int mt = 0; mt < 2; mt++)
            #pragma unroll
            for (int i = 0; i < 8; i++)
                #pragma unroll
                for (int j = 0; j < 4; j++) s[mt][i][j] = 0.f;
        #pragma unroll
        for (int ks = 0; ks < 8; ks++) {
            unsigned bb[8][2];
            #pragma unroll
            for (int nt = 0; nt < 8; nt++) {
                bb[nt][0] = Kb[(nt * 8 + gp) * 68 + ks * 8 + tq];
                bb[nt][1] = Kb[(nt * 8 + gp) * 68 + ks * 8 + tq + 4];
            }
            #pragma unroll
            for (int mt = 0; mt < 2; mt++)
                #pragma unroll
                for (int nt = 0; nt < 8; nt++)
                    mma8(s[mt][nt], qa[mt][ks], bb[nt][0], bb[nt][1]);
        }

        // online softmax per m-tile (scale = 1/sqrt(64) = 0.125 exactly)
        #pragma unroll
        for (int mt = 0; mt < 2; mt++) {
            float mx0 = -1e30f, mx1 = -1e30f;
            #pragma unroll
            for (int nt = 0; nt < 8; nt++) {
                s[mt][nt][0] *= 0.125f; s[mt][nt][1] *= 0.125f;
                s[mt][nt][2] *= 0.125f; s[mt][nt][3] *= 0.125f;
                mx0 = fmaxf(mx0, fmaxf(s[mt][nt][0], s[mt][nt][1]));
                mx1 = fmaxf(mx1, fmaxf(s[mt][nt][2], s[mt][nt][3]));
            }
            mx0 = fmaxf(mx0, __shfl_xor_sync(0xffffffffu, mx0, 1));
            mx0 = fmaxf(mx0, __shfl_xor_sync(0xffffffffu, mx0, 2));
            mx1 = fmaxf(mx1, __shfl_xor_sync(0xffffffffu, mx1, 1));
            mx1 = fmaxf(mx1, __shfl_xor_sync(0xffffffffu, mx1, 2));
            float mn0 = fmaxf(mrow[mt][0], mx0), mn1 = fmaxf(mrow[mt][1], mx1);
            float al0 = __expf(mrow[mt][0] - mn0), al1 = __expf(mrow[mt][1] - mn1);
            mrow[mt][0] = mn0; mrow[mt][1] = mn1;

            const int pr = w * 32 + mt * 16 + gp;
            float rs0 = 0.f, rs1 = 0.f;
            #pragma unroll
            for (int nt = 0; nt < 8; nt++) {
                float p0 = __expf(s[mt][nt][0] - mn0), p1 = __expf(s[mt][nt][1] - mn0);
                float p2 = __expf(s[mt][nt][2] - mn1), p3 = __expf(s[mt][nt][3] - mn1);
                rs0 += p0 + p1; rs1 += p2 + p3;
                int pc = nt * 8 + tq * 2;
                PsP[pr * 68 + pc]           = f2tf(p0);
                PsP[pr * 68 + pc + 1]       = f2tf(p1);
                PsP[(pr + 8) * 68 + pc]     = f2tf(p2);
                PsP[(pr + 8) * 68 + pc + 1] = f2tf(p3);
            }
            rs0 += __shfl_xor_sync(0xffffffffu, rs0, 1);
            rs0 += __shfl_xor_sync(0xffffffffu, rs0, 2);
            rs1 += __shfl_xor_sync(0xffffffffu, rs1, 1);
            rs1 += __shfl_xor_sync(0xffffffffu, rs1, 2);
            lrow[mt][0] = lrow[mt][0] * al0 + rs0;
            lrow[mt][1] = lrow[mt][1] * al1 + rs1;
            #pragma unroll
            for (int nt = 0; nt < 8; nt++) {
                o[mt][nt][0] *= al0; o[mt][nt][1] *= al0;
                o[mt][nt][2] *= al1; o[mt][nt][3] *= al1;
            }
        }
        __syncwarp();   // Ps rows are warp-private

        // O += P V   (V frags shared across mt; V already tf32 bits)
        #pragma unroll
        for (int ks = 0; ks < 8; ks++) {
            unsigned a[2][4];
            #pragma unroll
            for (int mt = 0; mt < 2; mt++) {
                const int pr = w * 32 + mt * 16 + gp;
                a[mt][0] = PsP[pr * 68 + ks * 8 + tq];
                a[mt][1] = PsP[(pr + 8) * 68 + ks * 8 + tq];
                a[mt][2] = PsP[pr * 68 + ks * 8 + tq + 4];
                a[mt][3] = PsP[(pr + 8) * 68 + ks * 8 + tq + 4];
            }
            #pragma unroll
            for (int nt = 0; nt < 8; nt++) {
                unsigned b0 = Vb[(ks * 8 + tq) * 72 + nt * 8 + gp];
                unsigned b1 = Vb[(ks * 8 + tq + 4) * 72 + nt * 8 + gp];
                #pragma unroll
                for (int mt = 0; mt < 2; mt++)
                    mma8(o[mt][nt], a[mt], b0, b1);
            }
        }

        if (kt + 1 < 32) CP_WAIT0();
        __syncthreads();
    }

    // epilogue: normalize, cvt to tf32 bits for the O-projection, scatter
    #pragma unroll
    for (int mt = 0; mt < 2; mt++) {
        float inv0 = 1.f / lrow[mt][0], inv1 = 1.f / lrow[mt][1];
        float* cp0 = C + (size_t)(b * SEQ + qbase + mt * 16 + gp) * HID + h * HD;
        float* cp1 = cp0 + (size_t)8 * HID;
        #pragma unroll
        for (int nt = 0; nt < 8; nt++) {
            int d = nt * 8 + tq * 2;
            *(float2*)&cp0[d] = make_float2(__uint_as_float(f2tf(o[mt][nt][0] * inv0)),
                                            __uint_as_float(f2tf(o[mt][nt][1] * inv0)));
            *(float2*)&cp1[d] = make_float2(__uint_as_float(f2tf(o[mt][nt][2] * inv1)),
                                            __uint_as_float(f2tf(o[mt][nt][3] * inv1)));
        }
    }
}

// ============================================================================
// Launch
// ============================================================================
extern "C" void kernel_launch(void* const* d_in, const int* in_sizes, int n_in,
                              void* d_out, int out_size)
{
    const float* x  = (const float*)d_in[0];
    const float* wq = (const float*)d_in[1];
    const float* bq = (const float*)d_in[2];
    const float* wk = (const float*)d_in[3];
    const float* bk = (const float*)d_in[4];
    const float* wv = (const float*)d_in[5];
    const float* bv = (const float*)d_in[6];
    const float* wo = (const float*)d_in[7];
    const float* bo = (const float*)d_in[8];
    float* out = (float*)d_out;

    float *Qp, *Kp, *Vp, *Cp, *Xt, *Wqt, *Wkt, *Wvt, *Wot;
    cudaGetSymbolAddress((void**)&Qp,  g_Q);
    cudaGetSymbolAddress((void**)&Kp,  g_K);
    cudaGetSymbolAddress((void**)&Vp,  g_V);
    cudaGetSymbolAddress((void**)&Cp,  g_C);
    cudaGetSymbolAddress((void**)&Xt,  g_xt);
    cudaGetSymbolAddress((void**)&Wqt, g_wqt);
    cudaGetSymbolAddress((void**)&Wkt, g_wkt);
    cudaGetSymbolAddress((void**)&Wvt, g_wvt);
    cudaGetSymbolAddress((void**)&Wot, g_wot);

    cudaFuncSetAttribute(gemm_q,  cudaFuncAttributeMaxDynamicSharedMemorySize, GEMM_SMEM);
    cudaFuncSetAttribute(gemm_o,  cudaFuncAttributeMaxDynamicSharedMemorySize, GEMM_SMEM);
    cudaFuncSetAttribute(gemm_kv, cudaFuncAttributeMaxDynamicSharedMemorySize, GEMM_SMEM);
    cudaFuncSetAttribute(attn_tf32, cudaFuncAttributeMaxDynamicSharedMemorySize, ATTN_SMEM);

    dim3 thr(256);

    // Pre-pass: convert inputs/weights to tf32 bit patterns (RNA, once)
    cvt_tf32<<<(MROWS * HID / 4 + 255) / 256, thr>>>((const float4*)x,  (float4*)Xt,  MROWS * HID / 4);
    cvt_tf32<<<(HID * HID / 4 + 255) / 256, thr>>>((const float4*)wq, (float4*)Wqt, HID * HID / 4);
    cvt_tf32<<<(KVD * HID / 4 + 255) / 256, thr>>>((const float4*)wk, (float4*)Wkt, KVD * HID / 4);
    cvt_tf32<<<(KVD * HID / 4 + 255) / 256, thr>>>((const float4*)wv, (float4*)Wvt, KVD * HID / 4);
    cvt_tf32<<<(HID * HID / 4 + 255) / 256, thr>>>((const float4*)wo, (float4*)Wot, HID * HID / 4);

    // Q projection: grid (8, 32); epilogue writes tf32 bits
    gemm_q<<<dim3(HID / 256, MROWS / 128), thr, GEMM_SMEM>>>(Xt, Wqt, bq, Qp, HID, HID);
    // K + V projections fused: grid (4, 32); epilogues write tf32 bits
    gemm_kv<<<dim3(2 * KVD / 256, MROWS / 128), thr, GEMM_SMEM>>>(
        Xt, Wkt, bk, Kp, Wvt, bv, Vp, KVD, HID);
    // attention: 512 CTAs; writes C as tf32 bits
    attn_tf32<<<BATCH * NH * (SEQ / 256), thr, ATTN_SMEM>>>(Qp, Kp, Vp, Cp);
    // output projection: plain fp32 output
    gemm_o<<<dim3(HID / 256, MROWS / 128), thr, GEMM_SMEM>>>(Cp, Wot, bo, out, HID, HID);
}